// round 15
// baseline (speedup 1.0000x reference)
#include <cuda_runtime.h>
#include <cuda_bf16.h>
#include <stdint.h>
#include <math.h>

// ---------------------------------------------------------------------------
// Problem constants
// ---------------------------------------------------------------------------
#define T_STEPS 512
#define BATCH   64
#define IN_DIM  1024
#define H_DIM   1024
#define G4      4096            // 4*H
#define KSPLIT  4               // split-K for the per-step GEMM
#define NBLK    128             // persistent-kernel grid (1 blk/SM, <=148 SMs)
#define NBAR    (2 * T_STEPS)   // grid barriers used per launch
#define NFLAG   8               // replicated release flags (spread LTS slices)
#define LDS_    40              // xproj smem leading dim (bf16)
#define LDW_    264             // resident-W / A smem leading dim (bf16); 528B rows

// Scratch (static __device__ arrays: allocation-free per harness rules)
__device__ float    g_xproj[(size_t)T_STEPS * BATCH * G4]; // input projection
__device__ float    g_part[KSPLIT * BATCH * G4];           // split-K partials
__device__ float    g_c[BATCH * H_DIM];                    // cell state
__device__ uint32_t g_hh[BATCH * 512];                     // h split hi (bf16x2 pairs)
__device__ uint32_t g_hl[BATCH * 512];                     // h split lo (bf16x2 pairs)
__device__ int      g_cnt[NBAR];                           // barrier arrival counters
__device__ int      g_flag[NBAR * NFLAG * 64];             // replicated release flags

// ---------------------------------------------------------------------------
// Grid barrier: single arrival counter; release replicated across 8 flag
// copies on distinct LTS slices (256B stride). Pollers split 16-per-copy and
// back off with __nanosleep so the poll rate never queues a slice.
// ---------------------------------------------------------------------------
__device__ __forceinline__ void grid_bar(int slot) {
    __syncthreads();
    if (threadIdx.x == 0) {
        __threadfence();
        int old = atomicAdd(&g_cnt[slot], 1);
        volatile int* flags = (volatile int*)&g_flag[slot * NFLAG * 64];
        if (old == NBLK - 1) {
#pragma unroll
            for (int i = 0; i < NFLAG; i++) flags[i * 64] = 1;
        } else {
            volatile int* my = &flags[(blockIdx.x & (NFLAG - 1)) * 64];
            while (*my == 0) __nanosleep(32);
        }
        __threadfence();
    }
    __syncthreads();
}

__global__ void zero_bar_k() {
    int i = blockIdx.x * 256 + threadIdx.x;
    if (i < NBAR) g_cnt[i] = 0;
    for (int j = i; j < NBAR * NFLAG * 64; j += gridDim.x * 256) g_flag[j] = 0;
}

// ---------------------------------------------------------------------------
// Tensor-core helpers: mma.sync m16n8k16 bf16 + ldmatrix
// ---------------------------------------------------------------------------
__device__ __forceinline__ uint32_t smem_u32(const void* p) {
    return (uint32_t)__cvta_generic_to_shared(p);
}

__device__ __forceinline__ void ldm_x4(uint32_t r[4], uint32_t a) {
    asm volatile("ldmatrix.sync.aligned.m8n8.x4.shared.b16 {%0,%1,%2,%3}, [%4];\n"
                 : "=r"(r[0]), "=r"(r[1]), "=r"(r[2]), "=r"(r[3]) : "r"(a));
}

__device__ __forceinline__ void mma_bf(float d[4], const uint32_t a[4], const uint32_t b[2]) {
    asm volatile(
        "mma.sync.aligned.m16n8k16.row.col.f32.bf16.bf16.f32 "
        "{%0,%1,%2,%3}, {%4,%5,%6,%7}, {%8,%9}, {%0,%1,%2,%3};\n"
        : "+f"(d[0]), "+f"(d[1]), "+f"(d[2]), "+f"(d[3])
        : "r"(a[0]), "r"(a[1]), "r"(a[2]), "r"(a[3]), "r"(b[0]), "r"(b[1]));
}

template <int LD>
__device__ __forceinline__ uint32_t a_addrT(uint32_t base, int m0, int k0, int lane) {
    int r = m0 + (lane & 7) + ((lane >> 3) & 1) * 8;
    int c = k0 + (lane >> 4) * 8;
    return base + (uint32_t)(r * LD + c) * 2u;
}
template <int LD>
__device__ __forceinline__ uint32_t b_addrT(uint32_t base, int n0, int k0, int lane) {
    int r = n0 + (lane & 7) + ((lane >> 4) & 1) * 8;
    int c = k0 + ((lane >> 3) & 1) * 8;
    return base + (uint32_t)(r * LD + c) * 2u;
}

// Split fp32x4 -> bf16 hi/lo x4, store to smem (4B-aligned positions)
__device__ __forceinline__ void split_store4(float4 v, __nv_bfloat16* hi, __nv_bfloat16* lo) {
    __nv_bfloat16 h0 = __float2bfloat16(v.x), h1 = __float2bfloat16(v.y);
    __nv_bfloat16 h2 = __float2bfloat16(v.z), h3 = __float2bfloat16(v.w);
    __nv_bfloat16 l0 = __float2bfloat16(v.x - __bfloat162float(h0));
    __nv_bfloat16 l1 = __float2bfloat16(v.y - __bfloat162float(h1));
    __nv_bfloat16 l2 = __float2bfloat16(v.z - __bfloat162float(h2));
    __nv_bfloat16 l3 = __float2bfloat16(v.w - __bfloat162float(h3));
    uint32_t* hp = (uint32_t*)hi;
    uint32_t* lp = (uint32_t*)lo;
    __nv_bfloat162 t0 = __halves2bfloat162(h0, h1);
    __nv_bfloat162 t1 = __halves2bfloat162(h2, h3);
    __nv_bfloat162 t2 = __halves2bfloat162(l0, l1);
    __nv_bfloat162 t3 = __halves2bfloat162(l2, l3);
    hp[0] = *(uint32_t*)&t0;
    hp[1] = *(uint32_t*)&t1;
    lp[0] = *(uint32_t*)&t2;
    lp[1] = *(uint32_t*)&t3;
}

// Split two fp32 -> packed bf16x2 hi and lo words
__device__ __forceinline__ void split_pack2(float a, float b, uint32_t& hi, uint32_t& lo) {
    __nv_bfloat16 ha = __float2bfloat16(a), hb = __float2bfloat16(b);
    __nv_bfloat16 la = __float2bfloat16(a - __bfloat162float(ha));
    __nv_bfloat16 lb = __float2bfloat16(b - __bfloat162float(hb));
    __nv_bfloat162 th = __halves2bfloat162(ha, hb);
    __nv_bfloat162 tl = __halves2bfloat162(la, lb);
    hi = *(uint32_t*)&th;
    lo = *(uint32_t*)&tl;
}

// ---------------------------------------------------------------------------
// Kernel: x_proj = input @ weight_ih^T   (split-bf16 mma.sync; R10 version)
// C[32768, 4096], BM=128, BN=128, BK=32, 256 thr, warps 4Mx2N (32x64 tiles)
// ---------------------------------------------------------------------------
__global__ __launch_bounds__(256) void xproj_gemm(const float* __restrict__ A,
                                                  const float* __restrict__ W) {
    __shared__ __align__(16) __nv_bfloat16 Ah[128 * LDS_], Al[128 * LDS_];
    __shared__ __align__(16) __nv_bfloat16 Bh[128 * LDS_], Bl[128 * LDS_];

    const int bn = blockIdx.x, bm = blockIdx.y, tid = threadIdx.x;
    const int wid = tid >> 5, lane = tid & 31;
    const int wm = (wid >> 1) * 32;
    const int wn = (wid & 1) * 64;

    float acc[2][8][4];
#pragma unroll
    for (int i = 0; i < 2; i++)
#pragma unroll
        for (int j = 0; j < 8; j++)
#pragma unroll
            for (int k = 0; k < 4; k++) acc[i][j][k] = 0.f;

    const float* Ab = A + (size_t)bm * 128 * IN_DIM;
    const float* Wb = W + (size_t)bn * 128 * IN_DIM;
    const int lr = tid >> 3;
    const int lc = (tid & 7) * 4;

    const uint32_t sAh = smem_u32(Ah), sAl = smem_u32(Al);
    const uint32_t sBh = smem_u32(Bh), sBl = smem_u32(Bl);

    float4 av[4], wv[4];
#pragma unroll
    for (int i = 0; i < 4; i++) {
        av[i] = *(const float4*)(Ab + (size_t)(lr + i * 32) * IN_DIM + lc);
        wv[i] = *(const float4*)(Wb + (size_t)(lr + i * 32) * IN_DIM + lc);
    }

    for (int kt = 0; kt < IN_DIM; kt += 32) {
#pragma unroll
        for (int i = 0; i < 4; i++) {
            int r = lr + i * 32;
            split_store4(av[i], &Ah[r * LDS_ + lc], &Al[r * LDS_ + lc]);
            split_store4(wv[i], &Bh[r * LDS_ + lc], &Bl[r * LDS_ + lc]);
        }
        __syncthreads();
        if (kt + 32 < IN_DIM) {
#pragma unroll
            for (int i = 0; i < 4; i++) {
                av[i] = *(const float4*)(Ab + (size_t)(lr + i * 32) * IN_DIM + kt + 32 + lc);
                wv[i] = *(const float4*)(Wb + (size_t)(lr + i * 32) * IN_DIM + kt + 32 + lc);
            }
        }
#pragma unroll
        for (int kk = 0; kk < 32; kk += 16) {
            uint32_t ah[2][4], al[2][4];
#pragma unroll
            for (int mf = 0; mf < 2; mf++) {
                ldm_x4(ah[mf], a_addrT<LDS_>(sAh, wm + mf * 16, kk, lane));
                ldm_x4(al[mf], a_addrT<LDS_>(sAl, wm + mf * 16, kk, lane));
            }
            uint32_t bh[8][2], bl[8][2];
#pragma unroll
            for (int np = 0; np < 4; np++) {
                uint32_t t[4];
                ldm_x4(t, b_addrT<LDS_>(sBh, wn + np * 16, kk, lane));
                bh[np * 2][0] = t[0]; bh[np * 2][1] = t[1];
                bh[np * 2 + 1][0] = t[2]; bh[np * 2 + 1][1] = t[3];
                ldm_x4(t, b_addrT<LDS_>(sBl, wn + np * 16, kk, lane));
                bl[np * 2][0] = t[0]; bl[np * 2][1] = t[1];
                bl[np * 2 + 1][0] = t[2]; bl[np * 2 + 1][1] = t[3];
            }
#pragma unroll
            for (int mf = 0; mf < 2; mf++)
#pragma unroll
                for (int nf = 0; nf < 8; nf++) {
                    mma_bf(acc[mf][nf], ah[mf], bh[nf]);
                    mma_bf(acc[mf][nf], ah[mf], bl[nf]);
                    mma_bf(acc[mf][nf], al[mf], bh[nf]);
                }
        }
        __syncthreads();
    }

    const int qr = lane >> 2, qc = (lane & 3) * 2;
    float* Cb = g_xproj + ((size_t)(bm * 128 + wm)) * G4 + bn * 128 + wn;
#pragma unroll
    for (int mf = 0; mf < 2; mf++)
#pragma unroll
        for (int nf = 0; nf < 8; nf++) {
            float* p = Cb + (size_t)(mf * 16 + qr) * G4 + nf * 8 + qc;
            *(float2*)p = make_float2(acc[mf][nf][0], acc[mf][nf][1]);
            *(float2*)(p + (size_t)8 * G4) = make_float2(acc[mf][nf][2], acc[mf][nf][3]);
        }
}

// ---------------------------------------------------------------------------
// Per-step GEMM with RESIDENT split-bf16 W in smem.
// t==0: load fp32 hidden + split. t>0: load pre-split bf16 pairs written by
// the pointwise (g_hh/g_hl) via __ldcg (addresses repeat across steps -> L1
// stale hazard) straight into smem; no conversion math.
// ---------------------------------------------------------------------------
__device__ __forceinline__ void step_gemm_res(
    int t, const float* __restrict__ hidden, int bn, int ks, int tid,
    __nv_bfloat16* Ah, __nv_bfloat16* Al,
    const __nv_bfloat16* Wh, const __nv_bfloat16* Wl) {
    const int k0 = ks * 256;

    if (t == 0) {
#pragma unroll
        for (int i = 0; i < 16; i++) {
            int idx = tid + i * 256;
            int n = idx >> 6, c4 = (idx & 63) * 4;
            float4 v = *(const float4*)(hidden + (size_t)n * H_DIM + k0 + c4);
            split_store4(v, &Ah[n * LDW_ + c4], &Al[n * LDW_ + c4]);
        }
    } else {
        // 64 rows x 128 bf16-pairs per array: 2048 uint4 each, 8 per thread.
#pragma unroll
        for (int i = 0; i < 8; i++) {
            int idx = tid + i * 256;
            int n = idx >> 5, c = idx & 31;     // row, uint4-col (4 pairs each)
            uint4 vh = __ldcg((const uint4*)(g_hh + n * 512 + ks * 128 + c * 4));
            uint4 vl = __ldcg((const uint4*)(g_hl + n * 512 + ks * 128 + c * 4));
            *(uint4*)&Ah[n * LDW_ + c * 8] = vh;
            *(uint4*)&Al[n * LDW_ + c * 8] = vl;
        }
    }
    __syncthreads();

    const int wid = tid >> 5, lane = tid & 31;
    const int wm = (wid >> 2) * 32;
    const int wn = (wid & 3) * 32;

    float acc[2][4][4];
#pragma unroll
    for (int i = 0; i < 2; i++)
#pragma unroll
        for (int j = 0; j < 4; j++)
#pragma unroll
            for (int k = 0; k < 4; k++) acc[i][j][k] = 0.f;

    const uint32_t sAh = smem_u32(Ah), sAl = smem_u32(Al);
    const uint32_t sWh = smem_u32(Wh), sWl = smem_u32(Wl);

#pragma unroll 4
    for (int kk = 0; kk < 256; kk += 16) {
        uint32_t ah[2][4], al[2][4];
#pragma unroll
        for (int mf = 0; mf < 2; mf++) {
            ldm_x4(ah[mf], a_addrT<LDW_>(sAh, wm + mf * 16, kk, lane));
            ldm_x4(al[mf], a_addrT<LDW_>(sAl, wm + mf * 16, kk, lane));
        }
        uint32_t bh[4][2], bl[4][2];
#pragma unroll
        for (int np = 0; np < 2; np++) {
            uint32_t t2[4];
            ldm_x4(t2, b_addrT<LDW_>(sWh, wn + np * 16, kk, lane));
            bh[np * 2][0] = t2[0]; bh[np * 2][1] = t2[1];
            bh[np * 2 + 1][0] = t2[2]; bh[np * 2 + 1][1] = t2[3];
            ldm_x4(t2, b_addrT<LDW_>(sWl, wn + np * 16, kk, lane));
            bl[np * 2][0] = t2[0]; bl[np * 2][1] = t2[1];
            bl[np * 2 + 1][0] = t2[2]; bl[np * 2 + 1][1] = t2[3];
        }
#pragma unroll
        for (int mf = 0; mf < 2; mf++)
#pragma unroll
            for (int nf = 0; nf < 4; nf++) {
                mma_bf(acc[mf][nf], ah[mf], bh[nf]);
                mma_bf(acc[mf][nf], ah[mf], bl[nf]);
                mma_bf(acc[mf][nf], al[mf], bh[nf]);
            }
    }

    const int qr = lane >> 2, qc = (lane & 3) * 2;
    float* P = g_part + (size_t)ks * BATCH * G4 + (size_t)wm * G4 + bn * 128 + wn;
#pragma unroll
    for (int mf = 0; mf < 2; mf++)
#pragma unroll
        for (int nf = 0; nf < 4; nf++) {
            float* p = P + (size_t)(mf * 16 + qr) * G4 + nf * 8 + qc;
            *(float2*)p = make_float2(acc[mf][nf][0], acc[mf][nf][1]);
            *(float2*)(p + (size_t)8 * G4) = make_float2(acc[mf][nf][2], acc[mf][nf][3]);
        }
}

// ---------------------------------------------------------------------------
// Pointwise / LayerNorm (vectorized, merged reductions, fast activations).
// One block per batch row b (bid < 64). Emits fp32 out + split-bf16 h pairs.
// ---------------------------------------------------------------------------
template <int N>
__device__ __forceinline__ void multi_red(float* v, float* sred) {
#pragma unroll
    for (int o = 16; o > 0; o >>= 1)
#pragma unroll
        for (int k = 0; k < N; k++) v[k] += __shfl_xor_sync(0xffffffffu, v[k], o);
    const int w = threadIdx.x >> 5;
    if ((threadIdx.x & 31) == 0)
#pragma unroll
        for (int k = 0; k < N; k++) sred[w * N + k] = v[k];
    __syncthreads();
#pragma unroll
    for (int k = 0; k < N; k++) {
        float s = 0.f;
#pragma unroll
        for (int w8 = 0; w8 < 8; w8++) s += sred[w8 * N + k];
        v[k] = s;
    }
    __syncthreads();
}

__device__ __forceinline__ float sigm(float x) { return 1.f / (1.f + __expf(-x)); }
__device__ __forceinline__ float tanh_f(float x) {
    // saturation-safe: x>>0 -> e=inf -> 1; x<<0 -> e=0 -> -1
    float e = __expf(2.f * x);
    return 1.f - 2.f / (e + 1.f);
}

__device__ __forceinline__ void step_point_dev(
    int t, int b, int tid, const float* __restrict__ cell0,
    const float* __restrict__ wch, const float* __restrict__ bias,
    const float* __restrict__ gf, const float* __restrict__ gi,
    const float* __restrict__ gg, const float* __restrict__ go,
    const float* __restrict__ gcell, const float* __restrict__ bcell,
    float* __restrict__ out, float* sred) {
    const float4* xp4 = (const float4*)(g_xproj + ((size_t)t * BATCH + b) * G4);
    const float4* p4  = (const float4*)(g_part + (size_t)b * G4);
    const int PS4 = BATCH * G4 / 4;

    float vf[4], vi[4], vg[4], vo[4];
#pragma unroll
    for (int g = 0; g < 4; g++) {
        float4 s = xp4[g * 256 + tid];
#pragma unroll
        for (int k = 0; k < KSPLIT; k++) {
            float4 q = __ldcg(&p4[k * PS4 + g * 256 + tid]);
            s.x += q.x; s.y += q.y; s.z += q.z; s.w += q.w;
        }
        float* dst = (g == 0) ? vf : (g == 1) ? vi : (g == 2) ? vg : vo;
        dst[0] = s.x; dst[1] = s.y; dst[2] = s.z; dst[3] = s.w;
    }

    const float4* wch4 = (const float4*)wch;
    float4 wcf = wch4[tid], wci = wch4[256 + tid], wco = wch4[512 + tid];
    float4 cold4 = (t == 0) ? ((const float4*)cell0)[b * 256 + tid]
                            : ((float4*)g_c)[b * 256 + tid];
    float cold[4] = {cold4.x, cold4.y, cold4.z, cold4.w};
    const float wcf_[4] = {wcf.x, wcf.y, wcf.z, wcf.w};
    const float wci_[4] = {wci.x, wci.y, wci.z, wci.w};
    const float wco_[4] = {wco.x, wco.y, wco.z, wco.w};

#pragma unroll
    for (int j = 0; j < 4; j++) {
        vf[j] += wcf_[j] * cold[j];
        vi[j] += wci_[j] * cold[j];
    }

    float r1[6] = {0.f, 0.f, 0.f, 0.f, 0.f, 0.f};
#pragma unroll
    for (int j = 0; j < 4; j++) {
        r1[0] += vf[j]; r1[1] += vf[j] * vf[j];
        r1[2] += vi[j]; r1[3] += vi[j] * vi[j];
        r1[4] += vg[j]; r1[5] += vg[j] * vg[j];
    }
    multi_red<6>(r1, sred);
    const float inv = 1.f / 1024.f;
    float mf = r1[0] * inv, rf = rsqrtf(r1[1] * inv - mf * mf + 1e-5f);
    float mi = r1[2] * inv, ri = rsqrtf(r1[3] * inv - mi * mi + 1e-5f);
    float mg = r1[4] * inv, rg = rsqrtf(r1[5] * inv - mg * mg + 1e-5f);

    float4 gf4 = ((const float4*)gf)[tid], gi4 = ((const float4*)gi)[tid];
    float4 gg4 = ((const float4*)gg)[tid], go4 = ((const float4*)go)[tid];
    float4 bf4 = ((const float4*)bias)[tid];
    float4 bi4 = ((const float4*)bias)[256 + tid];
    float4 bg4 = ((const float4*)bias)[512 + tid];
    float4 bo4 = ((const float4*)bias)[768 + tid];
    const float gf_[4] = {gf4.x, gf4.y, gf4.z, gf4.w};
    const float gi_[4] = {gi4.x, gi4.y, gi4.z, gi4.w};
    const float gg_[4] = {gg4.x, gg4.y, gg4.z, gg4.w};
    const float go_[4] = {go4.x, go4.y, go4.z, go4.w};
    const float bf_[4] = {bf4.x, bf4.y, bf4.z, bf4.w};
    const float bi_[4] = {bi4.x, bi4.y, bi4.z, bi4.w};
    const float bg_[4] = {bg4.x, bg4.y, bg4.z, bg4.w};
    const float bo_[4] = {bo4.x, bo4.y, bo4.z, bo4.w};

    float cn[4];
#pragma unroll
    for (int j = 0; j < 4; j++) {
        const float fj = sigm((vf[j] - mf) * rf * gf_[j] + bf_[j]);
        const float ij = sigm((vi[j] - mi) * ri * gi_[j] + bi_[j]);
        const float gj = tanh_f((vg[j] - mg) * rg * gg_[j] + bg_[j]);
        cn[j] = fj * cold[j] + ij * gj;
        vo[j] += wco_[j] * cn[j];
    }

    float r2[4] = {0.f, 0.f, 0.f, 0.f};
#pragma unroll
    for (int j = 0; j < 4; j++) {
        r2[0] += cn[j]; r2[1] += cn[j] * cn[j];
        r2[2] += vo[j]; r2[3] += vo[j] * vo[j];
    }
    multi_red<4>(r2, sred);
    float mc = r2[0] * inv, rc = rsqrtf(r2[1] * inv - mc * mc + 1e-5f);
    float mo = r2[2] * inv, ro = rsqrtf(r2[3] * inv - mo * mo + 1e-5f);

    float4 gc4v = ((const float4*)gcell)[tid];
    float4 bc4v = ((const float4*)bcell)[tid];
    const float gc_[4] = {gc4v.x, gc4v.y, gc4v.z, gc4v.w};
    const float bc_[4] = {bc4v.x, bc4v.y, bc4v.z, bc4v.w};

    float hn[4];
#pragma unroll
    for (int j = 0; j < 4; j++) {
        const float oj = sigm((vo[j] - mo) * ro * go_[j] + bo_[j]);
        const float cln = (cn[j] - mc) * rc * gc_[j] + bc_[j];
        hn[j] = oj * tanh_f(cln);
    }

    // fp32 output (the answer tensor)
    ((float4*)out)[((size_t)t * BATCH + b) * 256 + tid] =
        make_float4(hn[0], hn[1], hn[2], hn[3]);
    ((float4*)g_c)[b * 256 + tid] = make_float4(cn[0], cn[1], cn[2], cn[3]);

    // split-bf16 hand-off for next step's GEMM A tile
    uint32_t hh0, hl0, hh1, hl1;
    split_pack2(hn[0], hn[1], hh0, hl0);
    split_pack2(hn[2], hn[3], hh1, hl1);
    ((uint2*)g_hh)[b * 256 + tid] = make_uint2(hh0, hh1);
    ((uint2*)g_hl)[b * 256 + tid] = make_uint2(hl0, hl1);
}

// ---------------------------------------------------------------------------
// Persistent recurrence kernel. Dynamic smem: Wh|Wl (128 x LDW_) + Ah|Al (64 x LDW_)
// ---------------------------------------------------------------------------
#define SMEM_DYN_BYTES (2 * (128 * LDW_ + 64 * LDW_) * 2)

__global__ __launch_bounds__(256) void recur_persist(
    const float* __restrict__ hidden, const float* __restrict__ cell0,
    const float* __restrict__ Whh, const float* __restrict__ wch,
    const float* __restrict__ bias,
    const float* __restrict__ gf, const float* __restrict__ gi,
    const float* __restrict__ gg, const float* __restrict__ go,
    const float* __restrict__ gcell, const float* __restrict__ bcell,
    float* __restrict__ out) {
    extern __shared__ __nv_bfloat16 dsm[];
    __nv_bfloat16* Wh = dsm;
    __nv_bfloat16* Wl = dsm + 128 * LDW_;
    __nv_bfloat16* Ah = dsm + 2 * 128 * LDW_;
    __nv_bfloat16* Al = dsm + 2 * 128 * LDW_ + 64 * LDW_;
    __shared__ float sred[48];

    const int bid = blockIdx.x;
    const int tid = threadIdx.x;
    const int bn = bid & 31;
    const int ks = bid >> 5;

    // Prologue: convert this block's W chunk (128 x 256 fp32) once.
    {
        const float* Wb = Whh + (size_t)(bn * 128) * H_DIM + ks * 256;
#pragma unroll
        for (int i = 0; i < 32; i++) {
            int idx = tid + i * 256;
            int n = idx >> 6, c4 = (idx & 63) * 4;
            float4 v = *(const float4*)(Wb + (size_t)n * H_DIM + c4);
            split_store4(v, &Wh[n * LDW_ + c4], &Wl[n * LDW_ + c4]);
        }
        __syncthreads();
    }

    for (int t = 0; t < T_STEPS; t++) {
        step_gemm_res(t, hidden, bn, ks, tid, Ah, Al, Wh, Wl);
        grid_bar(2 * t);
        if (bid < BATCH)
            step_point_dev(t, bid, tid, cell0, wch, bias, gf, gi, gg, go, gcell, bcell, out, sred);
        grid_bar(2 * t + 1);
    }

    // Finalize: h_f = out[T-1], c_f = g_c (appended after out), float4.
    const size_t base4 = (size_t)T_STEPS * BATCH * H_DIM / 4;
    float4* out4 = (float4*)out;
    const int tot4 = BATCH * H_DIM / 4;
    for (int i = bid * 256 + tid; i < tot4; i += NBLK * 256) {
        out4[base4 + i] = out4[(size_t)(T_STEPS - 1) * BATCH * H_DIM / 4 + i];
        out4[base4 + tot4 + i] = __ldcg(&((float4*)g_c)[i]);
    }
}

// ---------------------------------------------------------------------------
extern "C" void kernel_launch(void* const* d_in, const int* in_sizes, int n_in,
                              void* d_out, int out_size) {
    const float* input  = (const float*)d_in[0];
    const float* hidden = (const float*)d_in[1];
    const float* cell   = (const float*)d_in[2];
    const float* wih    = (const float*)d_in[3];
    const float* whh    = (const float*)d_in[4];
    const float* wch    = (const float*)d_in[5];
    const float* bias   = (const float*)d_in[6];
    const float* gf     = (const float*)d_in[7];
    const float* gi     = (const float*)d_in[8];
    const float* gg     = (const float*)d_in[9];
    const float* go     = (const float*)d_in[10];
    const float* gcell  = (const float*)d_in[11];
    const float* bcell  = (const float*)d_in[12];
    float* out = (float*)d_out;

    cudaFuncSetAttribute(recur_persist,
                         cudaFuncAttributeMaxDynamicSharedMemorySize,
                         SMEM_DYN_BYTES);

    // 3-node graph: barrier reset, x_proj GEMM, persistent recurrence.
    zero_bar_k<<<64, 256>>>();
    xproj_gemm<<<dim3(G4 / 128, (T_STEPS * BATCH) / 128), 256>>>(input, wih);
    recur_persist<<<NBLK, 256, SMEM_DYN_BYTES>>>(hidden, cell, whh, wch, bias,
                                                 gf, gi, gg, go, gcell, bcell, out);
}

// round 16
// speedup vs baseline: 1.0539x; 1.0539x over previous
#include <cuda_runtime.h>
#include <cuda_bf16.h>
#include <stdint.h>
#include <math.h>

// ---------------------------------------------------------------------------
// Problem constants
// ---------------------------------------------------------------------------
#define T_STEPS 512
#define BATCH   64
#define IN_DIM  1024
#define H_DIM   1024
#define G4      4096            // 4*H
#define KSPLIT  4               // split-K for the per-step GEMM
#define NBLK    128             // persistent-kernel grid (1 blk/SM, <=148 SMs)
#define NBAR    (2 * T_STEPS + 1)  // grid barriers used per launch
#define LDS_    40              // xproj smem leading dim (bf16)
#define LDW_    264             // resident-W / A smem leading dim (bf16); 528B rows

// Scratch (static __device__ arrays: allocation-free per harness rules)
__device__ float g_xproj[(size_t)T_STEPS * BATCH * G4];   // input projection
__device__ float g_part[KSPLIT * BATCH * G4];             // split-K partials
__device__ float g_c[BATCH * H_DIM];                      // final cell state
__device__ int   g_cnt[NBAR];                             // barrier arrival counters
__device__ int   g_flag[NBAR];                            // barrier release flags

// ---------------------------------------------------------------------------
// Grid barrier (R12-proven single counter + flag + nanosleep), with role
// split: n_arr blocks arrive; only waiters poll. Slots zeroed per launch.
// ---------------------------------------------------------------------------
__device__ __forceinline__ void grid_bar(int slot, int n_arr, bool i_arrive, bool i_wait) {
    __syncthreads();
    if (threadIdx.x == 0) {
        __threadfence();
        if (i_arrive) {
            int old = atomicAdd(&g_cnt[slot], 1);
            if (old == n_arr - 1) *((volatile int*)&g_flag[slot]) = 1;
        }
        if (i_wait) {
            while (*((volatile int*)&g_flag[slot]) == 0) __nanosleep(32);
        }
        __threadfence();
    }
    __syncthreads();
}

__global__ void zero_bar_k() {
    int i = blockIdx.x * 256 + threadIdx.x;
    if (i < NBAR) { g_cnt[i] = 0; g_flag[i] = 0; }
}

// ---------------------------------------------------------------------------
// Tensor-core helpers: mma.sync m16n8k16 bf16 + ldmatrix
// ---------------------------------------------------------------------------
__device__ __forceinline__ uint32_t smem_u32(const void* p) {
    return (uint32_t)__cvta_generic_to_shared(p);
}

__device__ __forceinline__ void ldm_x4(uint32_t r[4], uint32_t a) {
    asm volatile("ldmatrix.sync.aligned.m8n8.x4.shared.b16 {%0,%1,%2,%3}, [%4];\n"
                 : "=r"(r[0]), "=r"(r[1]), "=r"(r[2]), "=r"(r[3]) : "r"(a));
}

__device__ __forceinline__ void mma_bf(float d[4], const uint32_t a[4], const uint32_t b[2]) {
    asm volatile(
        "mma.sync.aligned.m16n8k16.row.col.f32.bf16.bf16.f32 "
        "{%0,%1,%2,%3}, {%4,%5,%6,%7}, {%8,%9}, {%0,%1,%2,%3};\n"
        : "+f"(d[0]), "+f"(d[1]), "+f"(d[2]), "+f"(d[3])
        : "r"(a[0]), "r"(a[1]), "r"(a[2]), "r"(a[3]), "r"(b[0]), "r"(b[1]));
}

template <int LD>
__device__ __forceinline__ uint32_t a_addrT(uint32_t base, int m0, int k0, int lane) {
    int r = m0 + (lane & 7) + ((lane >> 3) & 1) * 8;
    int c = k0 + (lane >> 4) * 8;
    return base + (uint32_t)(r * LD + c) * 2u;
}
template <int LD>
__device__ __forceinline__ uint32_t b_addrT(uint32_t base, int n0, int k0, int lane) {
    int r = n0 + (lane & 7) + ((lane >> 4) & 1) * 8;
    int c = k0 + ((lane >> 3) & 1) * 8;
    return base + (uint32_t)(r * LD + c) * 2u;
}

// Split fp32x4 -> bf16 hi/lo x4, store to smem (4B-aligned positions)
__device__ __forceinline__ void split_store4(float4 v, __nv_bfloat16* hi, __nv_bfloat16* lo) {
    __nv_bfloat16 h0 = __float2bfloat16(v.x), h1 = __float2bfloat16(v.y);
    __nv_bfloat16 h2 = __float2bfloat16(v.z), h3 = __float2bfloat16(v.w);
    __nv_bfloat16 l0 = __float2bfloat16(v.x - __bfloat162float(h0));
    __nv_bfloat16 l1 = __float2bfloat16(v.y - __bfloat162float(h1));
    __nv_bfloat16 l2 = __float2bfloat16(v.z - __bfloat162float(h2));
    __nv_bfloat16 l3 = __float2bfloat16(v.w - __bfloat162float(h3));
    uint32_t* hp = (uint32_t*)hi;
    uint32_t* lp = (uint32_t*)lo;
    __nv_bfloat162 t0 = __halves2bfloat162(h0, h1);
    __nv_bfloat162 t1 = __halves2bfloat162(h2, h3);
    __nv_bfloat162 t2 = __halves2bfloat162(l0, l1);
    __nv_bfloat162 t3 = __halves2bfloat162(l2, l3);
    hp[0] = *(uint32_t*)&t0;
    hp[1] = *(uint32_t*)&t1;
    lp[0] = *(uint32_t*)&t2;
    lp[1] = *(uint32_t*)&t3;
}

// ---------------------------------------------------------------------------
// Kernel: x_proj = input @ weight_ih^T   (split-bf16 mma.sync; R10/R12 exact)
// ---------------------------------------------------------------------------
__global__ __launch_bounds__(256) void xproj_gemm(const float* __restrict__ A,
                                                  const float* __restrict__ W) {
    __shared__ __align__(16) __nv_bfloat16 Ah[128 * LDS_], Al[128 * LDS_];
    __shared__ __align__(16) __nv_bfloat16 Bh[128 * LDS_], Bl[128 * LDS_];

    const int bn = blockIdx.x, bm = blockIdx.y, tid = threadIdx.x;
    const int wid = tid >> 5, lane = tid & 31;
    const int wm = (wid >> 1) * 32;
    const int wn = (wid & 1) * 64;

    float acc[2][8][4];
#pragma unroll
    for (int i = 0; i < 2; i++)
#pragma unroll
        for (int j = 0; j < 8; j++)
#pragma unroll
            for (int k = 0; k < 4; k++) acc[i][j][k] = 0.f;

    const float* Ab = A + (size_t)bm * 128 * IN_DIM;
    const float* Wb = W + (size_t)bn * 128 * IN_DIM;
    const int lr = tid >> 3;
    const int lc = (tid & 7) * 4;

    const uint32_t sAh = smem_u32(Ah), sAl = smem_u32(Al);
    const uint32_t sBh = smem_u32(Bh), sBl = smem_u32(Bl);

    float4 av[4], wv[4];
#pragma unroll
    for (int i = 0; i < 4; i++) {
        av[i] = *(const float4*)(Ab + (size_t)(lr + i * 32) * IN_DIM + lc);
        wv[i] = *(const float4*)(Wb + (size_t)(lr + i * 32) * IN_DIM + lc);
    }

    for (int kt = 0; kt < IN_DIM; kt += 32) {
#pragma unroll
        for (int i = 0; i < 4; i++) {
            int r = lr + i * 32;
            split_store4(av[i], &Ah[r * LDS_ + lc], &Al[r * LDS_ + lc]);
            split_store4(wv[i], &Bh[r * LDS_ + lc], &Bl[r * LDS_ + lc]);
        }
        __syncthreads();
        if (kt + 32 < IN_DIM) {
#pragma unroll
            for (int i = 0; i < 4; i++) {
                av[i] = *(const float4*)(Ab + (size_t)(lr + i * 32) * IN_DIM + kt + 32 + lc);
                wv[i] = *(const float4*)(Wb + (size_t)(lr + i * 32) * IN_DIM + kt + 32 + lc);
            }
        }
#pragma unroll
        for (int kk = 0; kk < 32; kk += 16) {
            uint32_t ah[2][4], al[2][4];
#pragma unroll
            for (int mf = 0; mf < 2; mf++) {
                ldm_x4(ah[mf], a_addrT<LDS_>(sAh, wm + mf * 16, kk, lane));
                ldm_x4(al[mf], a_addrT<LDS_>(sAl, wm + mf * 16, kk, lane));
            }
            uint32_t bh[8][2], bl[8][2];
#pragma unroll
            for (int np = 0; np < 4; np++) {
                uint32_t t[4];
                ldm_x4(t, b_addrT<LDS_>(sBh, wn + np * 16, kk, lane));
                bh[np * 2][0] = t[0]; bh[np * 2][1] = t[1];
                bh[np * 2 + 1][0] = t[2]; bh[np * 2 + 1][1] = t[3];
                ldm_x4(t, b_addrT<LDS_>(sBl, wn + np * 16, kk, lane));
                bl[np * 2][0] = t[0]; bl[np * 2][1] = t[1];
                bl[np * 2 + 1][0] = t[2]; bl[np * 2 + 1][1] = t[3];
            }
#pragma unroll
            for (int mf = 0; mf < 2; mf++)
#pragma unroll
                for (int nf = 0; nf < 8; nf++) {
                    mma_bf(acc[mf][nf], ah[mf], bh[nf]);
                    mma_bf(acc[mf][nf], ah[mf], bl[nf]);
                    mma_bf(acc[mf][nf], al[mf], bh[nf]);
                }
        }
        __syncthreads();
    }

    const int qr = lane >> 2, qc = (lane & 3) * 2;
    float* Cb = g_xproj + ((size_t)(bm * 128 + wm)) * G4 + bn * 128 + wn;
#pragma unroll
    for (int mf = 0; mf < 2; mf++)
#pragma unroll
        for (int nf = 0; nf < 8; nf++) {
            float* p = Cb + (size_t)(mf * 16 + qr) * G4 + nf * 8 + qc;
            *(float2*)p = make_float2(acc[mf][nf][0], acc[mf][nf][1]);
            *(float2*)(p + (size_t)8 * G4) = make_float2(acc[mf][nf][2], acc[mf][nf][3]);
        }
}

// ---------------------------------------------------------------------------
// Per-step GEMM with RESIDENT split-bf16 W in smem (R12 exact: fp32 h load).
// ---------------------------------------------------------------------------
__device__ __forceinline__ void step_gemm_res(
    const float* __restrict__ h, int bn, int ks, int tid,
    __nv_bfloat16* Ah, __nv_bfloat16* Al,
    const __nv_bfloat16* Wh, const __nv_bfloat16* Wl) {
    const int k0 = ks * 256;

#pragma unroll
    for (int i = 0; i < 16; i++) {
        int idx = tid + i * 256;
        int n = idx >> 6, c4 = (idx & 63) * 4;
        float4 v = *(const float4*)(h + (size_t)n * H_DIM + k0 + c4);
        split_store4(v, &Ah[n * LDW_ + c4], &Al[n * LDW_ + c4]);
    }
    __syncthreads();

    const int wid = tid >> 5, lane = tid & 31;
    const int wm = (wid >> 2) * 32;
    const int wn = (wid & 3) * 32;

    float acc[2][4][4];
#pragma unroll
    for (int i = 0; i < 2; i++)
#pragma unroll
        for (int j = 0; j < 4; j++)
#pragma unroll
            for (int k = 0; k < 4; k++) acc[i][j][k] = 0.f;

    const uint32_t sAh = smem_u32(Ah), sAl = smem_u32(Al);
    const uint32_t sWh = smem_u32(Wh), sWl = smem_u32(Wl);

#pragma unroll 4
    for (int kk = 0; kk < 256; kk += 16) {
        uint32_t ah[2][4], al[2][4];
#pragma unroll
        for (int mf = 0; mf < 2; mf++) {
            ldm_x4(ah[mf], a_addrT<LDW_>(sAh, wm + mf * 16, kk, lane));
            ldm_x4(al[mf], a_addrT<LDW_>(sAl, wm + mf * 16, kk, lane));
        }
        uint32_t bh[4][2], bl[4][2];
#pragma unroll
        for (int np = 0; np < 2; np++) {
            uint32_t t2[4];
            ldm_x4(t2, b_addrT<LDW_>(sWh, wn + np * 16, kk, lane));
            bh[np * 2][0] = t2[0]; bh[np * 2][1] = t2[1];
            bh[np * 2 + 1][0] = t2[2]; bh[np * 2 + 1][1] = t2[3];
            ldm_x4(t2, b_addrT<LDW_>(sWl, wn + np * 16, kk, lane));
            bl[np * 2][0] = t2[0]; bl[np * 2][1] = t2[1];
            bl[np * 2 + 1][0] = t2[2]; bl[np * 2 + 1][1] = t2[3];
        }
#pragma unroll
        for (int mf = 0; mf < 2; mf++)
#pragma unroll
            for (int nf = 0; nf < 4; nf++) {
                mma_bf(acc[mf][nf], ah[mf], bh[nf]);
                mma_bf(acc[mf][nf], ah[mf], bl[nf]);
                mma_bf(acc[mf][nf], al[mf], bh[nf]);
            }
    }

    const int qr = lane >> 2, qc = (lane & 3) * 2;
    float* P = g_part + (size_t)ks * BATCH * G4 + (size_t)wm * G4 + bn * 128 + wn;
#pragma unroll
    for (int mf = 0; mf < 2; mf++)
#pragma unroll
        for (int nf = 0; nf < 4; nf++) {
            float* p = P + (size_t)(mf * 16 + qr) * G4 + nf * 8 + qc;
            *(float2*)p = make_float2(acc[mf][nf][0], acc[mf][nf][1]);
            *(float2*)(p + (size_t)8 * G4) = make_float2(acc[mf][nf][2], acc[mf][nf][3]);
        }
}

// ---------------------------------------------------------------------------
// Pointwise / LayerNorm (R12 math, c in registers, xp pre-fetched).
// ---------------------------------------------------------------------------
template <int N>
__device__ __forceinline__ void multi_red(float* v, float* sred) {
#pragma unroll
    for (int o = 16; o > 0; o >>= 1)
#pragma unroll
        for (int k = 0; k < N; k++) v[k] += __shfl_xor_sync(0xffffffffu, v[k], o);
    const int w = threadIdx.x >> 5;
    if ((threadIdx.x & 31) == 0)
#pragma unroll
        for (int k = 0; k < N; k++) sred[w * N + k] = v[k];
    __syncthreads();
#pragma unroll
    for (int k = 0; k < N; k++) {
        float s = 0.f;
#pragma unroll
        for (int w8 = 0; w8 < 8; w8++) s += sred[w8 * N + k];
        v[k] = s;
    }
    __syncthreads();
}

__device__ __forceinline__ float sigm(float x) { return 1.f / (1.f + expf(-x)); }

__device__ __forceinline__ void step_point_dev(
    int t, int b, int tid, const float4 xpre[4], float cold[4],
    const float* __restrict__ wch, const float* __restrict__ bias,
    const float* __restrict__ gf, const float* __restrict__ gi,
    const float* __restrict__ gg, const float* __restrict__ go,
    const float* __restrict__ gcell, const float* __restrict__ bcell,
    float* __restrict__ out, float* sred) {
    const float4* p4 = (const float4*)(g_part + (size_t)b * G4);
    const int PS4 = BATCH * G4 / 4;

    float vf[4], vi[4], vg[4], vo[4];
#pragma unroll
    for (int g = 0; g < 4; g++) {
        float4 s = xpre[g];
#pragma unroll
        for (int k = 0; k < KSPLIT; k++) {
            float4 q = __ldcg(&p4[k * PS4 + g * 256 + tid]);
            s.x += q.x; s.y += q.y; s.z += q.z; s.w += q.w;
        }
        float* dst = (g == 0) ? vf : (g == 1) ? vi : (g == 2) ? vg : vo;
        dst[0] = s.x; dst[1] = s.y; dst[2] = s.z; dst[3] = s.w;
    }

    const float4* wch4 = (const float4*)wch;
    float4 wcf = wch4[tid], wci = wch4[256 + tid], wco = wch4[512 + tid];
    const float wcf_[4] = {wcf.x, wcf.y, wcf.z, wcf.w};
    const float wci_[4] = {wci.x, wci.y, wci.z, wci.w};
    const float wco_[4] = {wco.x, wco.y, wco.z, wco.w};

#pragma unroll
    for (int j = 0; j < 4; j++) {
        vf[j] += wcf_[j] * cold[j];
        vi[j] += wci_[j] * cold[j];
    }

    float r1[6] = {0.f, 0.f, 0.f, 0.f, 0.f, 0.f};
#pragma unroll
    for (int j = 0; j < 4; j++) {
        r1[0] += vf[j]; r1[1] += vf[j] * vf[j];
        r1[2] += vi[j]; r1[3] += vi[j] * vi[j];
        r1[4] += vg[j]; r1[5] += vg[j] * vg[j];
    }
    multi_red<6>(r1, sred);
    const float inv = 1.f / 1024.f;
    float mf = r1[0] * inv, rf = rsqrtf(r1[1] * inv - mf * mf + 1e-5f);
    float mi = r1[2] * inv, ri = rsqrtf(r1[3] * inv - mi * mi + 1e-5f);
    float mg = r1[4] * inv, rg = rsqrtf(r1[5] * inv - mg * mg + 1e-5f);

    float4 gf4 = ((const float4*)gf)[tid], gi4 = ((const float4*)gi)[tid];
    float4 gg4 = ((const float4*)gg)[tid], go4 = ((const float4*)go)[tid];
    float4 bf4 = ((const float4*)bias)[tid];
    float4 bi4 = ((const float4*)bias)[256 + tid];
    float4 bg4 = ((const float4*)bias)[512 + tid];
    float4 bo4 = ((const float4*)bias)[768 + tid];
    const float gf_[4] = {gf4.x, gf4.y, gf4.z, gf4.w};
    const float gi_[4] = {gi4.x, gi4.y, gi4.z, gi4.w};
    const float gg_[4] = {gg4.x, gg4.y, gg4.z, gg4.w};
    const float go_[4] = {go4.x, go4.y, go4.z, go4.w};
    const float bf_[4] = {bf4.x, bf4.y, bf4.z, bf4.w};
    const float bi_[4] = {bi4.x, bi4.y, bi4.z, bi4.w};
    const float bg_[4] = {bg4.x, bg4.y, bg4.z, bg4.w};
    const float bo_[4] = {bo4.x, bo4.y, bo4.z, bo4.w};

    float cn[4];
#pragma unroll
    for (int j = 0; j < 4; j++) {
        const float fj = sigm((vf[j] - mf) * rf * gf_[j] + bf_[j]);
        const float ij = sigm((vi[j] - mi) * ri * gi_[j] + bi_[j]);
        const float gj = tanhf((vg[j] - mg) * rg * gg_[j] + bg_[j]);
        cn[j] = fj * cold[j] + ij * gj;
        vo[j] += wco_[j] * cn[j];
    }

    float r2[4] = {0.f, 0.f, 0.f, 0.f};
#pragma unroll
    for (int j = 0; j < 4; j++) {
        r2[0] += cn[j]; r2[1] += cn[j] * cn[j];
        r2[2] += vo[j]; r2[3] += vo[j] * vo[j];
    }
    multi_red<4>(r2, sred);
    float mc = r2[0] * inv, rc = rsqrtf(r2[1] * inv - mc * mc + 1e-5f);
    float mo = r2[2] * inv, ro = rsqrtf(r2[3] * inv - mo * mo + 1e-5f);

    float4 gc4v = ((const float4*)gcell)[tid];
    float4 bc4v = ((const float4*)bcell)[tid];
    const float gc_[4] = {gc4v.x, gc4v.y, gc4v.z, gc4v.w};
    const float bc_[4] = {bc4v.x, bc4v.y, bc4v.z, bc4v.w};

    float hn[4];
#pragma unroll
    for (int j = 0; j < 4; j++) {
        const float oj = sigm((vo[j] - mo) * ro * go_[j] + bo_[j]);
        const float cln = (cn[j] - mc) * rc * gc_[j] + bc_[j];
        hn[j] = oj * tanhf(cln);
        cold[j] = cn[j];           // cell state stays in registers
    }

    ((float4*)out)[((size_t)t * BATCH + b) * 256 + tid] =
        make_float4(hn[0], hn[1], hn[2], hn[3]);
}

// ---------------------------------------------------------------------------
// Persistent recurrence kernel. Dynamic smem: Wh|Wl (128 x LDW_) + Ah|Al (64 x LDW_)
// ---------------------------------------------------------------------------
#define SMEM_DYN_BYTES (2 * (128 * LDW_ + 64 * LDW_) * 2)

__global__ __launch_bounds__(256) void recur_persist(
    const float* __restrict__ hidden, const float* __restrict__ cell0,
    const float* __restrict__ Whh, const float* __restrict__ wch,
    const float* __restrict__ bias,
    const float* __restrict__ gf, const float* __restrict__ gi,
    const float* __restrict__ gg, const float* __restrict__ go,
    const float* __restrict__ gcell, const float* __restrict__ bcell,
    float* __restrict__ out) {
    extern __shared__ __nv_bfloat16 dsm[];
    __nv_bfloat16* Wh = dsm;
    __nv_bfloat16* Wl = dsm + 128 * LDW_;
    __nv_bfloat16* Ah = dsm + 2 * 128 * LDW_;
    __nv_bfloat16* Al = dsm + 2 * 128 * LDW_ + 64 * LDW_;
    __shared__ float sred[48];

    const int bid = blockIdx.x;
    const int tid = threadIdx.x;
    const int bn = bid & 31;
    const int ks = bid >> 5;
    const bool is_pw = (bid < BATCH);

    // Prologue: convert this block's W chunk (128 x 256 fp32) once.
    {
        const float* Wb = Whh + (size_t)(bn * 128) * H_DIM + ks * 256;
#pragma unroll
        for (int i = 0; i < 32; i++) {
            int idx = tid + i * 256;
            int n = idx >> 6, c4 = (idx & 63) * 4;
            float4 v = *(const float4*)(Wb + (size_t)n * H_DIM + c4);
            split_store4(v, &Wh[n * LDW_ + c4], &Wl[n * LDW_ + c4]);
        }
        __syncthreads();
    }

    // Cell state in registers for pointwise blocks.
    float cold[4] = {0.f, 0.f, 0.f, 0.f};
    if (is_pw) {
        float4 c0 = ((const float4*)cell0)[bid * 256 + tid];
        cold[0] = c0.x; cold[1] = c0.y; cold[2] = c0.z; cold[3] = c0.w;
    }

    for (int t = 0; t < T_STEPS; t++) {
        const float* h = (t == 0) ? hidden : out + (size_t)(t - 1) * BATCH * H_DIM;
        step_gemm_res(h, bn, ks, tid, Ah, Al, Wh, Wl);

        // Prefetch this step's xproj gates; latency hides under bar1 wait.
        float4 xpre[4];
        if (is_pw) {
            const float4* xp4 = (const float4*)(g_xproj + ((size_t)t * BATCH + bid) * G4);
#pragma unroll
            for (int g = 0; g < 4; g++) xpre[g] = xp4[g * 256 + tid];
        }

        // bar1: all 128 GEMMs arrive; only pointwise blocks need to wait.
        grid_bar(2 * t, NBLK, true, is_pw);

        if (is_pw)
            step_point_dev(t, bid, tid, xpre, cold, wch, bias,
                           gf, gi, gg, go, gcell, bcell, out, sred);

        // bar2: only the 64 pointwise blocks arrive; everyone waits for h(t).
        grid_bar(2 * t + 1, BATCH, is_pw, true);
    }

    // Write final cell state once, then full rendezvous before finalize.
    if (is_pw) {
        ((float4*)g_c)[bid * 256 + tid] =
            make_float4(cold[0], cold[1], cold[2], cold[3]);
    }
    grid_bar(2 * T_STEPS, NBLK, true, true);

    // Finalize: h_f = out[T-1], c_f = g_c (appended after out), float4.
    const size_t base4 = (size_t)T_STEPS * BATCH * H_DIM / 4;
    float4* out4 = (float4*)out;
    const int tot4 = BATCH * H_DIM / 4;
    for (int i = bid * 256 + tid; i < tot4; i += NBLK * 256) {
        out4[base4 + i] = out4[(size_t)(T_STEPS - 1) * BATCH * H_DIM / 4 + i];
        out4[base4 + tot4 + i] = __ldcg(&((float4*)g_c)[i]);
    }
}

// ---------------------------------------------------------------------------
extern "C" void kernel_launch(void* const* d_in, const int* in_sizes, int n_in,
                              void* d_out, int out_size) {
    const float* input  = (const float*)d_in[0];
    const float* hidden = (const float*)d_in[1];
    const float* cell   = (const float*)d_in[2];
    const float* wih    = (const float*)d_in[3];
    const float* whh    = (const float*)d_in[4];
    const float* wch    = (const float*)d_in[5];
    const float* bias   = (const float*)d_in[6];
    const float* gf     = (const float*)d_in[7];
    const float* gi     = (const float*)d_in[8];
    const float* gg     = (const float*)d_in[9];
    const float* go     = (const float*)d_in[10];
    const float* gcell  = (const float*)d_in[11];
    const float* bcell  = (const float*)d_in[12];
    float* out = (float*)d_out;

    cudaFuncSetAttribute(recur_persist,
                         cudaFuncAttributeMaxDynamicSharedMemorySize,
                         SMEM_DYN_BYTES);

    // 3-node graph: barrier reset, x_proj GEMM, persistent recurrence.
    zero_bar_k<<<(NBAR + 255) / 256, 256>>>();
    xproj_gemm<<<dim3(G4 / 128, (T_STEPS * BATCH) / 128), 256>>>(input, wih);
    recur_persist<<<NBLK, 256, SMEM_DYN_BYTES>>>(hidden, cell, whh, wch, bias,
                                                 gf, gi, gg, go, gcell, bcell, out);
}